// round 16
// baseline (speedup 1.0000x reference)
#include <cuda_runtime.h>

typedef unsigned long long u64;

#define BATCH 64
#define TLEN  2048
#define TM1   2047
#define CIN   8
#define MD    16
#define NOUT  10

#define CHUNK  64
#define NCHUNK 32            // 32*64 = 2048 >= 2047 (tail -> identity)
#define NGRP   8             // 16-thread groups per block
#define SPG    8             // steps per group
#define STR    20            // padded row stride (floats)
#define SLOT   (MD*STR)      // 320 floats per matrix slot
#define GSTR   (2*SLOT + 4)  // per-group region: S/scratch slot + Z slot + pad

// chunk partial products: [B][NCHUNK][16][16]
__device__ float g_partial[BATCH * NCHUNK * MD * MD];

// ---- packed f32x2 helpers (Blackwell FFMA2 path) ----
__device__ __forceinline__ float2 unpk(u64 v) {
  float2 r; asm("mov.b64 {%0,%1}, %2;" : "=f"(r.x), "=f"(r.y) : "l"(v)); return r;
}
__device__ __forceinline__ u64 pk2(float x, float y) {
  u64 r; asm("mov.b64 %0, {%1,%2};" : "=l"(r) : "f"(x), "f"(y)); return r;
}
__device__ __forceinline__ u64 bc2(float x) {
  u64 r; asm("mov.b64 %0, {%1,%1};" : "=l"(r) : "f"(x)); return r;
}
__device__ __forceinline__ void fma2(u64& d, u64 a, u64 b) {
  asm("fma.rn.f32x2 %0, %1, %2, %0;" : "+l"(d) : "l"(a), "l"(b));
}
__device__ __forceinline__ u64 fma2v(u64 a, u64 b, u64 c) {
  u64 d; asm("fma.rn.f32x2 %0, %1, %2, %3;" : "=l"(d) : "l"(a), "l"(b), "l"(c)); return d;
}
__device__ __forceinline__ u64 mul2(u64 a, u64 b) {
  u64 d; asm("mul.rn.f32x2 %0, %1, %2;" : "=l"(d) : "l"(a), "l"(b)); return d;
}

// acc += av * Brow (16 floats in smem, 16B-aligned)
__device__ __forceinline__ void row_fma(u64* acc, u64 av, const float* brow) {
  const ulonglong2* bp = reinterpret_cast<const ulonglong2*>(brow);
  ulonglong2 b0 = bp[0], b1 = bp[1], b2 = bp[2], b3 = bp[3];
  fma2(acc[0], av, b0.x); fma2(acc[1], av, b0.y);
  fma2(acc[2], av, b1.x); fma2(acc[3], av, b1.y);
  fma2(acc[4], av, b2.x); fma2(acc[5], av, b2.y);
  fma2(acc[6], av, b3.x); fma2(acc[7], av, b3.y);
}

// acc(row) += a(row, packed regs) @ Bm (16x16 in smem, row stride STR)
__device__ __forceinline__ void mm_row2(const float* __restrict__ Bm,
                                        const u64* __restrict__ a,
                                        u64* __restrict__ acc) {
#pragma unroll
  for (int kp = 0; kp < 8; kp++) {
    float2 ak = unpk(a[kp]);
    row_fma(acc, bc2(ak.x), Bm + (2 * kp) * STR);
    row_fma(acc, bc2(ak.y), Bm + (2 * kp + 1) * STR);
  }
}

__device__ __forceinline__ void store_row2(float* dst, const u64* v) {
  ulonglong2* dp = reinterpret_cast<ulonglong2*>(dst);
  dp[0] = make_ulonglong2(v[0], v[1]);
  dp[1] = make_ulonglong2(v[2], v[3]);
  dp[2] = make_ulonglong2(v[4], v[5]);
  dp[3] = make_ulonglong2(v[6], v[7]);
}
__device__ __forceinline__ void load_row2(const float* src, u64* v) {
  const ulonglong2* sp = reinterpret_cast<const ulonglong2*>(src);
  ulonglong2 a = sp[0], b = sp[1], c = sp[2], d = sp[3];
  v[0] = a.x; v[1] = a.y; v[2] = b.x; v[3] = b.y;
  v[4] = c.x; v[5] = c.y; v[6] = d.x; v[7] = d.y;
}

// ---------------------------------------------------------------------------
// Kernel 1: per (batch, chunk of 64 steps): build S, expm via commuting-
// Horner Taylor-6 (theta<=0.25) + warp-uniform squarings, fold, block tree.
// 16-thread groups, 1 row/thread. Champion configuration (measured 440.4us):
// full-unroll mm, no launch_bounds cap (ptxas 255 regs, 2 CTAs/SM).
// ---------------------------------------------------------------------------
__global__ void __launch_bounds__(128) dev_chunks(const float* __restrict__ X,
                                                  const float* __restrict__ A) {
  __shared__ __align__(16) float Gs[CIN * SLOT];          // A - A^T per channel
  __shared__ __align__(16) float slots[NGRP * GSTR];      // 2 slots/group
  __shared__ float dxs[CHUNK * CIN];

  const int tid   = threadIdx.x;
  const int chunk = blockIdx.x;
  const int b     = blockIdx.y;
  const int base  = chunk * CHUNK;

  for (int idx = tid; idx < CIN * MD * MD; idx += 128) {
    int c = idx >> 8;
    int i = (idx >> 4) & 15;
    int j = idx & 15;
    Gs[c * SLOT + i * STR + j] =
        A[(i * MD + j) * CIN + c] - A[(j * MD + i) * CIN + c];
  }
  for (int idx = tid; idx < CHUNK * CIN; idx += 128) {
    int k = idx >> 3;
    int c = idx & 7;
    int t = base + k;
    float v = 0.f;
    if (t < TM1)
      v = X[(b * TLEN + t + 1) * CIN + c] - X[(b * TLEN + t) * CIN + c];
    dxs[idx] = v;
  }
  __syncthreads();

  const int grp = tid >> 4;
  const int li  = tid & 15;
  float* gS = slots + grp * GSTR;   // S / squaring scratch
  float* gZ = gS + SLOT;            // running product Z

  // identity row (packed), per thread
  u64 idp[8];
#pragma unroll
  for (int p = 0; p < 8; p++)
    idp[p] = pk2((li == 2 * p) ? 1.f : 0.f, (li == 2 * p + 1) ? 1.f : 0.f);

  u64 cur[8];

  for (int kl = 0; kl < SPG; kl++) {
    const int kk = grp * SPG + kl;

    // ---- S row (packed) ----
    u64 S[8];
#pragma unroll
    for (int p = 0; p < 8; p++) S[p] = 0ull;
#pragma unroll
    for (int c = 0; c < CIN; c++) {
      u64 d2 = bc2(dxs[kk * CIN + c]);
      row_fma(S, d2, Gs + c * SLOT + li * STR);
    }

    // ---- norm: min(inf-norm, Frobenius/sqrt(2)); warp-uniform s ----
    float rs = 0.f, fr = 0.f;
#pragma unroll
    for (int p = 0; p < 8; p++) {
      float2 t = unpk(S[p]);
      rs += fabsf(t.x) + fabsf(t.y);
      fr = fmaf(t.x, t.x, fr);
      fr = fmaf(t.y, t.y, fr);
    }
#pragma unroll
    for (int off = 1; off < 16; off <<= 1) {         // within 16-lane group
      rs = fmaxf(rs, __shfl_xor_sync(0xffffffffu, rs, off));
      fr += __shfl_xor_sync(0xffffffffu, fr, off);
    }
    float nrm = fminf(rs, sqrtf(0.5f * fr));
    nrm = fmaxf(nrm, __shfl_xor_sync(0xffffffffu, nrm, 16));  // warp-uniform
    int s = 0;
    if (nrm > 0.f) {
      int e;
      frexpf(nrm, &e);   // nrm = f * 2^e, f in [0.5,1)
      s = e + 2;         // ||S/2^s|| <= 0.25
      if (s < 0) s = 0;
      if (s > 40) s = 40;
    }
    const u64 sc2 = bc2(__int_as_float((127 - s) << 23));  // exact 2^-s
#pragma unroll
    for (int p = 0; p < 8; p++) S[p] = mul2(S[p], sc2);

    // store S once (prior readers of gS are this group's own threads; warp
    // flow is uniform, so full-warp syncs are legal and cheap)
    __syncwarp();
    store_row2(gS + li * STR, S);
    __syncwarp();

    // ---- Taylor-6 Horner via commutativity: cur stays in registers ----
    // P = I + S(I + S/2(I + S/3(I + S/4(I + S/5(I + S/6)))));  cur@S == S@cur
    {
      const u64 c6 = bc2(1.f / 6.f);
#pragma unroll
      for (int p = 0; p < 8; p++) cur[p] = fma2v(S[p], c6, idp[p]);
    }
#pragma unroll
    for (int k = 5; k >= 1; k--) {
      u64 acc[8];
#pragma unroll
      for (int p = 0; p < 8; p++) acc[p] = 0ull;
      mm_row2(gS, cur, acc);                  // acc = cur @ S  (== S @ cur)
      const u64 inv = bc2(1.f / (float)k);
#pragma unroll
      for (int p = 0; p < 8; p++) cur[p] = fma2v(acc[p], inv, idp[p]);
    }

    // ---- warp-uniform squarings (scratch = gS, S no longer needed) ----
    for (int q = 0; q < s; q++) {
      __syncwarp();
      store_row2(gS + li * STR, cur);
      __syncwarp();
      u64 acc[8];
#pragma unroll
      for (int p = 0; p < 8; p++) acc[p] = 0ull;
      mm_row2(gS, cur, acc);
#pragma unroll
      for (int p = 0; p < 8; p++) cur[p] = acc[p];
    }

    // ---- fold: Z = M @ Z ----
    if (kl > 0) {
      u64 acc[8];
#pragma unroll
      for (int p = 0; p < 8; p++) acc[p] = 0ull;
      mm_row2(gZ, cur, acc);                  // rows of M (regs) @ Z (smem)
#pragma unroll
      for (int p = 0; p < 8; p++) cur[p] = acc[p];
    }
    __syncwarp();
    store_row2(gZ + li * STR, cur);
    __syncwarp();
  }

  // ---- block tree over 8 group products (later factor on the left) ----
  __syncthreads();
  for (int cnt = NGRP; cnt > 1; cnt >>= 1) {
    int pairs = cnt >> 1;
    u64 acc[8];
    bool act = (grp < pairs);
    if (act) {
      u64 lrow[8];
      load_row2(slots + (2 * grp + 1) * GSTR + SLOT + li * STR, lrow);
#pragma unroll
      for (int p = 0; p < 8; p++) acc[p] = 0ull;
      mm_row2(slots + (2 * grp) * GSTR + SLOT, lrow, acc);
    }
    __syncthreads();
    if (act) store_row2(slots + grp * GSTR + SLOT + li * STR, acc);
    __syncthreads();
  }

  const float* Zf = slots + SLOT;  // group 0's Z slot
  for (int idx = tid; idx < MD * MD; idx += 128) {
    int i = idx >> 4, j = idx & 15;
    g_partial[(b * NCHUNK + chunk) * (MD * MD) + idx] = Zf[i * STR + j];
  }
}

// ---------------------------------------------------------------------------
// Kernel 2: per batch — tree over 32 chunk products, then linear head.
// ---------------------------------------------------------------------------
__global__ void __launch_bounds__(256) dev_finalize(const float* __restrict__ W,
                                                    const float* __restrict__ bias,
                                                    float* __restrict__ out) {
  __shared__ __align__(16) float bufs[NCHUNK * SLOT];  // 40 KB
  const int tid = threadIdx.x;
  const int b   = blockIdx.x;

  for (int idx = tid; idx < NCHUNK * MD * MD; idx += 256) {
    int cm = idx >> 8;
    int r  = idx & 255;
    bufs[cm * SLOT + (r >> 4) * STR + (r & 15)] =
        g_partial[b * NCHUNK * (MD * MD) + idx];
  }
  __syncthreads();

  const int grp = tid >> 4;
  const int li  = tid & 15;
  for (int cnt = NCHUNK; cnt > 1; cnt >>= 1) {
    int pairs = cnt >> 1;
    u64 acc[8];
    if (grp < pairs) {
      u64 lrow[8];
      load_row2(bufs + (2 * grp + 1) * SLOT + li * STR, lrow);
#pragma unroll
      for (int p = 0; p < 8; p++) acc[p] = 0ull;
      mm_row2(bufs + (2 * grp) * SLOT, lrow, acc);
    }
    __syncthreads();
    if (grp < pairs) store_row2(bufs + grp * SLOT + li * STR, acc);
    __syncthreads();
  }

  if (tid < NOUT * 16) {
    const int o = tid >> 4;
    float p = 0.f;
#pragma unroll
    for (int j = 0; j < 16; j++)
      p = fmaf(bufs[li * STR + j], W[o * 256 + li * 16 + j], p);
#pragma unroll
    for (int off = 8; off > 0; off >>= 1)
      p += __shfl_xor_sync(0xffffffffu, p, off);
    if (li == 0) out[b * NOUT + o] = p + bias[o];
  }
}

extern "C" void kernel_launch(void* const* d_in, const int* in_sizes, int n_in,
                              void* d_out, int out_size) {
  const float* X = nullptr; const float* A = nullptr;
  const float* W = nullptr; const float* bv = nullptr;
  for (int i = 0; i < n_in; i++) {
    const float* p = (const float*)d_in[i];
    switch (in_sizes[i]) {
      case BATCH * TLEN * CIN: X = p; break;   // 1048576
      case MD * MD * CIN:      A = p; break;   // 2048
      case NOUT * MD * MD:     W = p; break;   // 2560
      case NOUT:               bv = p; break;  // 10
      default: break;
    }
  }
  float* out = (float*)d_out;

  dim3 g1(NCHUNK, BATCH);
  dev_chunks<<<g1, 128>>>(X, A);
  dev_finalize<<<BATCH, 256>>>(W, bv, out);
}